// round 3
// baseline (speedup 1.0000x reference)
#include <cuda_runtime.h>
#include <math.h>

#define BB 8
#define CC 256
#define LL 2048
#define HH 4
#define HD 64
#define NTOK (BB*LL)
#define BHN (BB*HH)

__device__ float g_Q[BHN*LL*HD];
__device__ float g_K[BHN*LL*HD];
__device__ float g_V[BHN*LL*HD];
__device__ float g_G[BHN*HD*HD];
__device__ float g_AT[NTOK*CC];

__device__ __forceinline__ float exp_poly(float t) {
    float p = 2.48015873e-5f;
    p = fmaf(p, t, 1.98412698e-4f);
    p = fmaf(p, t, 1.38888889e-3f);
    p = fmaf(p, t, 8.33333333e-3f);
    p = fmaf(p, t, 4.16666667e-2f);
    p = fmaf(p, t, 1.66666667e-1f);
    p = fmaf(p, t, 0.5f);
    p = fmaf(p, t, 1.0f);
    p = fmaf(p, t, 1.0f);
    return p;
}

__device__ __forceinline__ float gelu_exact(float x) {
    return 0.5f * x * (1.0f + erff(x * 0.70710678118654752f));
}

__global__ void zero_G_kernel() {
    int n = BHN*HD*HD;
    for (int i = blockIdx.x*blockDim.x + threadIdx.x; i < n; i += gridDim.x*blockDim.x)
        g_G[i] = 0.f;
}

// ---------------- fused MLP: gelu(x@w1+b1)@w2+b2 -> Q/K/V [bh][l][d] --------
__global__ void __launch_bounds__(256) mlp_kernel(
    const float* __restrict__ x,
    const float* __restrict__ qw1, const float* __restrict__ qb1,
    const float* __restrict__ qw2, const float* __restrict__ qb2,
    const float* __restrict__ kw1, const float* __restrict__ kb1,
    const float* __restrict__ kw2, const float* __restrict__ kb2,
    const float* __restrict__ vw1, const float* __restrict__ vb1,
    const float* __restrict__ vw2, const float* __restrict__ vb2)
{
    extern __shared__ float sm[];
    float* xt = sm;                // [256][36]
    float* ht = sm + 256*36;       // [256][36]
    float* ws = sm + 2*256*36;     // [32][256]

    const float *w1, *b1, *w2, *b2; float* out;
    if (blockIdx.y == 0)      { w1=qw1; b1=qb1; w2=qw2; b2=qb2; out=g_Q; }
    else if (blockIdx.y == 1) { w1=kw1; b1=kb1; w2=kw2; b2=kb2; out=g_K; }
    else                      { w1=vw1; b1=vb1; w2=vw2; b2=vb2; out=g_V; }

    const int b  = blockIdx.x >> 6;
    const int l0 = (blockIdx.x & 63) << 5;
    const int tid = threadIdx.x;

    const float* xb = x + (size_t)b*CC*LL + l0;
    #pragma unroll
    for (int r = 0; r < 32; r++) {
        int idx = tid + r*256;
        xt[(idx >> 5)*36 + (idx & 31)] = xb[(size_t)(idx >> 5)*LL + (idx & 31)];
    }

    const int tg = tid >> 5, fg = tid & 31;
    const int t0 = tg << 2;

    float acc[4][8];
    #pragma unroll
    for (int m = 0; m < 4; m++)
        #pragma unroll
        for (int j = 0; j < 8; j++) acc[m][j] = 0.f;

    for (int ks = 0; ks < 8; ks++) {
        __syncthreads();
        const float4* wsrc = (const float4*)(w1 + ks*32*256);
        float4* wdst = (float4*)ws;
        #pragma unroll
        for (int r = 0; r < 8; r++) wdst[tid + r*256] = wsrc[tid + r*256];
        __syncthreads();
        #pragma unroll 8
        for (int k = 0; k < 32; k++) {
            float4 a = *(const float4*)(xt + (ks*32 + k)*36 + t0);
            #pragma unroll
            for (int j = 0; j < 8; j++) {
                float bv = ws[k*256 + fg + (j<<5)];
                acc[0][j] = fmaf(a.x, bv, acc[0][j]);
                acc[1][j] = fmaf(a.y, bv, acc[1][j]);
                acc[2][j] = fmaf(a.z, bv, acc[2][j]);
                acc[3][j] = fmaf(a.w, bv, acc[3][j]);
            }
        }
    }
    __syncthreads();
    #pragma unroll
    for (int j = 0; j < 8; j++) {
        int f = fg + (j<<5);
        float bbv = b1[f];
        float4 v;
        v.x = gelu_exact(acc[0][j] + bbv);
        v.y = gelu_exact(acc[1][j] + bbv);
        v.z = gelu_exact(acc[2][j] + bbv);
        v.w = gelu_exact(acc[3][j] + bbv);
        *(float4*)(ht + f*36 + t0) = v;
        acc[0][j]=0.f; acc[1][j]=0.f; acc[2][j]=0.f; acc[3][j]=0.f;
    }

    for (int ks = 0; ks < 8; ks++) {
        __syncthreads();
        const float4* wsrc = (const float4*)(w2 + ks*32*256);
        float4* wdst = (float4*)ws;
        #pragma unroll
        for (int r = 0; r < 8; r++) wdst[tid + r*256] = wsrc[tid + r*256];
        __syncthreads();
        #pragma unroll 8
        for (int k = 0; k < 32; k++) {
            float4 a = *(const float4*)(ht + (ks*32 + k)*36 + t0);
            #pragma unroll
            for (int j = 0; j < 8; j++) {
                float bv = ws[k*256 + fg + (j<<5)];
                acc[0][j] = fmaf(a.x, bv, acc[0][j]);
                acc[1][j] = fmaf(a.y, bv, acc[1][j]);
                acc[2][j] = fmaf(a.z, bv, acc[2][j]);
                acc[3][j] = fmaf(a.w, bv, acc[3][j]);
            }
        }
    }

    #pragma unroll
    for (int j = 0; j < 8; j++) {
        int f = fg + (j<<5);
        int h = f >> 6, d = f & 63;
        float bbv = b2[f];
        float* op = out + (((size_t)(b*HH + h))*LL + l0 + t0)*HD + d;
        #pragma unroll
        for (int m = 0; m < 4; m++) op[m*HD] = acc[m][j] + bbv;
    }
}

// ---------------- Gram: G[bh] = K^T K --------------------------------------
__global__ void __launch_bounds__(256) gram_kernel() {
    __shared__ float Ks[64*68];
    const int bh = blockIdx.x, sl = blockIdx.y;
    const float* Kb = g_K + ((size_t)bh*LL + sl*256)*HD;
    const int tid = threadIdx.x;
    const int d0 = (tid >> 4) << 2, e0 = (tid & 15) << 2;
    float acc[4][4];
    #pragma unroll
    for (int i = 0; i < 4; i++)
        #pragma unroll
        for (int j = 0; j < 4; j++) acc[i][j] = 0.f;

    for (int kt = 0; kt < 4; kt++) {
        __syncthreads();
        #pragma unroll
        for (int r = 0; r < 16; r++) {
            int idx = tid + r*256;
            Ks[(idx >> 6)*68 + (idx & 63)] = Kb[kt*64*HD + idx];
        }
        __syncthreads();
        #pragma unroll 8
        for (int k = 0; k < 64; k++) {
            float4 a  = *(const float4*)(Ks + k*68 + d0);
            float4 bv = *(const float4*)(Ks + k*68 + e0);
            float av[4] = {a.x, a.y, a.z, a.w};
            float bw[4] = {bv.x, bv.y, bv.z, bv.w};
            #pragma unroll
            for (int i = 0; i < 4; i++)
                #pragma unroll
                for (int j = 0; j < 4; j++)
                    acc[i][j] = fmaf(av[i], bw[j], acc[i][j]);
        }
    }
    float* Gp = g_G + (size_t)bh*HD*HD;
    #pragma unroll
    for (int i = 0; i < 4; i++)
        #pragma unroll
        for (int j = 0; j < 4; j++)
            atomicAdd(Gp + (d0 + i)*HD + e0 + j, acc[i][j]);
}

// ---------------- single-pass attention -------------------------------------
#define ATT_SMEM_BYTES ((64*132 + 64*132 + 128*68 + 128*132 + 3*128)*4)
__global__ void __launch_bounds__(256, 1) attn_kernel() {
    extern __shared__ float sm[];
    float* Qt   = sm;                   // [64][132]
    float* Kt   = Qt + 64*132;          // [64][132]
    float* Vs   = Kt + 64*132;          // [128][68]
    float* Pt   = Vs + 128*68;          // [128][132]
    float* invd = Pt + 128*132;
    float* psum = invd + 128;
    float* red  = psum + 128;

    const int tid = threadIdx.x;
    const int bh  = blockIdx.y;
    const int q0g = blockIdx.x << 7;

    const float* Qb = g_Q + ((size_t)bh*LL + q0g)*HD;
    #pragma unroll
    for (int r = 0; r < 32; r++) {
        int idx = tid + r*256;
        Qt[(idx & 63)*132 + (idx >> 6)] = Qb[idx];
    }
    {
        const float* Gb = g_G + (size_t)bh*HD*HD;
        #pragma unroll
        for (int r = 0; r < 16; r++) {
            int idx = tid + r*256;
            Pt[(idx >> 6)*68 + (idx & 63)] = Gb[idx];
        }
    }
    __syncthreads();

    {   // denom: ssq[q] = q^T G q on raw dots; arg = dot/(sqrt(ssq)+8e-12)
        const float* Gs = Pt;
        int q = tid & 127, half = tid >> 7;
        float part = 0.f;
        for (int d = half*32; d < half*32 + 32; d++) {
            float qd = Qt[d*132 + q];
            float t = 0.f;
            #pragma unroll 16
            for (int e = 0; e < 64; e++)
                t = fmaf(Gs[d*68 + e], Qt[e*132 + q], t);
            part = fmaf(qd, t, part);
        }
        if (half == 0) red[q] = part;
        __syncthreads();
        if (half == 1) {
            float ssq = red[q] + part;
            invd[q] = 1.0f / (sqrtf(fmaxf(ssq, 0.f)) + 8.0e-12f);
            psum[q] = 0.f;
        }
    }
    __syncthreads();

    const int ty = tid >> 4, tx = tid & 15;
    const int qr = ty << 3, kc = tx << 3, dc = tx << 2;

    float Oacc[8][4];
    #pragma unroll
    for (int i = 0; i < 8; i++)
        #pragma unroll
        for (int c = 0; c < 4; c++) Oacc[i][c] = 0.f;
    float psr[8] = {0,0,0,0,0,0,0,0};
    float idv[8];
    #pragma unroll
    for (int i = 0; i < 8; i++) idv[i] = invd[qr + i];

    const float* Kb = g_K + (size_t)bh*LL*HD;
    const float* Vb = g_V + (size_t)bh*LL*HD;

    for (int kt = 0; kt < 16; kt++) {
        __syncthreads();
        const float* Ksrc = Kb + (size_t)kt*128*HD;
        const float* Vsrc = Vb + (size_t)kt*128*HD;
        #pragma unroll
        for (int r = 0; r < 32; r++) {
            int idx = tid + r*256;
            Kt[(idx & 63)*132 + (idx >> 6)] = Ksrc[idx];
            Vs[(idx >> 6)*68 + (idx & 63)]  = Vsrc[idx];
        }
        __syncthreads();

        float s[8][8];
        #pragma unroll
        for (int i = 0; i < 8; i++)
            #pragma unroll
            for (int j = 0; j < 8; j++) s[i][j] = 0.f;
        #pragma unroll 4
        for (int d = 0; d < 64; d++) {
            float qf[8], kf[8];
            *(float4*)(qf)     = *(const float4*)(Qt + d*132 + qr);
            *(float4*)(qf + 4) = *(const float4*)(Qt + d*132 + qr + 4);
            *(float4*)(kf)     = *(const float4*)(Kt + d*132 + kc);
            *(float4*)(kf + 4) = *(const float4*)(Kt + d*132 + kc + 4);
            #pragma unroll
            for (int i = 0; i < 8; i++)
                #pragma unroll
                for (int j = 0; j < 8; j++)
                    s[i][j] = fmaf(qf[i], kf[j], s[i][j]);
        }
        #pragma unroll
        for (int i = 0; i < 8; i++) {
            float rs = 0.f;
            #pragma unroll
            for (int j = 0; j < 8; j++) {
                float p = exp_poly(s[i][j] * idv[i]);
                s[i][j] = p;
                rs += p;
            }
            psr[i] += rs;
        }
        #pragma unroll
        for (int j = 0; j < 8; j++) {
            *(float4*)(Pt + (kc + j)*132 + qr)     = make_float4(s[0][j], s[1][j], s[2][j], s[3][j]);
            *(float4*)(Pt + (kc + j)*132 + qr + 4) = make_float4(s[4][j], s[5][j], s[6][j], s[7][j]);
        }
        __syncthreads();

        #pragma unroll 4
        for (int k = 0; k < 128; k++) {
            float pf[8];
            *(float4*)(pf)     = *(const float4*)(Pt + k*132 + qr);
            *(float4*)(pf + 4) = *(const float4*)(Pt + k*132 + qr + 4);
            float4 vf = *(const float4*)(Vs + k*68 + dc);
            #pragma unroll
            for (int i = 0; i < 8; i++) {
                Oacc[i][0] = fmaf(pf[i], vf.x, Oacc[i][0]);
                Oacc[i][1] = fmaf(pf[i], vf.y, Oacc[i][1]);
                Oacc[i][2] = fmaf(pf[i], vf.z, Oacc[i][2]);
                Oacc[i][3] = fmaf(pf[i], vf.w, Oacc[i][3]);
            }
        }
    }

    #pragma unroll
    for (int i = 0; i < 8; i++) atomicAdd(&psum[qr + i], psr[i]);
    __syncthreads();

    const int b = bh >> 2, h = bh & 3;
    #pragma unroll
    for (int i = 0; i < 8; i++) {
        float inv = 1.0f / psum[qr + i];
        size_t row = (size_t)(b*LL + q0g + qr + i)*CC + h*HD + dc;
        *(float4*)(g_AT + row) = make_float4(Oacc[i][0]*inv, Oacc[i][1]*inv,
                                             Oacc[i][2]*inv, Oacc[i][3]*inv);
    }
}

// ---------------- O-proj + LayerNorm + ELU + residual + transpose -----------
__global__ void __launch_bounds__(256) out_kernel(
    const float* __restrict__ x_in, const float* __restrict__ ow,
    const float* __restrict__ ob, const float* __restrict__ lng,
    const float* __restrict__ lnb, float* __restrict__ out)
{
    extern __shared__ float sm[];
    float* at = sm;               // [256][36]  (k-major, tokens padded)
    float* ws = sm + 256*36;      // [32][256]

    const int tok0 = blockIdx.x << 5;
    const int b = tok0 >> 11, l0 = tok0 & (LL-1);
    const int tid = threadIdx.x;

    #pragma unroll
    for (int r = 0; r < 32; r++) {
        int idx = tid + r*256;
        int t = idx >> 8, k = idx & 255;
        at[k*36 + t] = g_AT[(size_t)(tok0 + t)*CC + k];
    }

    const int tg = tid >> 5, fg = tid & 31;
    const int t0 = tg << 2;

    float acc[4][8];
    #pragma unroll
    for (int m = 0; m < 4; m++)
        #pragma unroll
        for (int j = 0; j < 8; j++) acc[m][j] = 0.f;

    for (int ks = 0; ks < 8; ks++) {
        __syncthreads();
        const float4* wsrc = (const float4*)(ow + ks*32*256);
        float4* wdst = (float4*)ws;
        #pragma unroll
        for (int r = 0; r < 8; r++) wdst[tid + r*256] = wsrc[tid + r*256];
        __syncthreads();
        #pragma unroll 8
        for (int k = 0; k < 32; k++) {
            float4 a = *(const float4*)(at + (ks*32 + k)*36 + t0);
            #pragma unroll
            for (int j = 0; j < 8; j++) {
                float bv = ws[k*256 + fg + (j<<5)];
                acc[0][j] = fmaf(a.x, bv, acc[0][j]);
                acc[1][j] = fmaf(a.y, bv, acc[1][j]);
                acc[2][j] = fmaf(a.z, bv, acc[2][j]);
                acc[3][j] = fmaf(a.w, bv, acc[3][j]);
            }
        }
    }

    // bias + LayerNorm (warp = 32 lanes all share the same 4 tokens)
    float gv[8], bvv[8];
    #pragma unroll
    for (int j = 0; j < 8; j++) {
        int f = fg + (j<<5);
        acc[0][j] += ob[f]; acc[1][j] += ob[f]; acc[2][j] += ob[f]; acc[3][j] += ob[f];
        gv[j] = lng[f]; bvv[j] = lnb[f];
    }
    __syncthreads();   // 'at' reuse below
    #pragma unroll
    for (int m = 0; m < 4; m++) {
        float s = 0.f, s2 = 0.f;
        #pragma unroll
        for (int j = 0; j < 8; j++) { s += acc[m][j]; s2 = fmaf(acc[m][j], acc[m][j], s2); }
        #pragma unroll
        for (int o = 16; o > 0; o >>= 1) {
            s  += __shfl_xor_sync(0xffffffffu, s,  o);
            s2 += __shfl_xor_sync(0xffffffffu, s2, o);
        }
        float mu = s * (1.0f/256.0f);
        float var = fmaf(-mu, mu, s2 * (1.0f/256.0f));
        float rstd = rsqrtf(var + 1e-5f);
        #pragma unroll
        for (int j = 0; j < 8; j++) {
            int f = fg + (j<<5);
            at[f*36 + t0 + m] = fmaf((acc[m][j] - mu) * rstd, gv[j], bvv[j]);
        }
    }
    __syncthreads();

    // coalesced write: out[b][f][l0+t] = elu(y) + x_in
    const float* xb = x_in + (size_t)b*CC*LL + l0;
    float* outb = out + (size_t)b*CC*LL + l0;
    #pragma unroll
    for (int r = 0; r < 32; r++) {
        int idx = tid + r*256;
        int t = idx & 31, f = idx >> 5;
        float y = at[f*36 + t];
        float e = (y > 0.f) ? y : expm1f(y);
        outb[(size_t)f*LL + t] = e + xb[(size_t)f*LL + t];
    }
}

extern "C" void kernel_launch(void* const* d_in, const int* in_sizes, int n_in,
                              void* d_out, int out_size) {
    const float* x    = (const float*)d_in[0];
    const float* qw1  = (const float*)d_in[1];
    const float* qb1  = (const float*)d_in[2];
    const float* qw2  = (const float*)d_in[3];
    const float* qb2  = (const float*)d_in[4];
    const float* kw1  = (const float*)d_in[5];
    const float* kb1  = (const float*)d_in[6];
    const float* kw2  = (const float*)d_in[7];
    const float* kb2  = (const float*)d_in[8];
    const float* vw1  = (const float*)d_in[9];
    const float* vb1  = (const float*)d_in[10];
    const float* vw2  = (const float*)d_in[11];
    const float* vb2  = (const float*)d_in[12];
    const float* ow   = (const float*)d_in[13];
    const float* ob   = (const float*)d_in[14];
    const float* lng  = (const float*)d_in[15];
    const float* lnb  = (const float*)d_in[16];
    float* out = (float*)d_out;

    const int mlp_smem = (2*256*36 + 32*256)*4;
    const int out_smem = (256*36 + 32*256)*4;
    cudaFuncSetAttribute(mlp_kernel,  cudaFuncAttributeMaxDynamicSharedMemorySize, mlp_smem);
    cudaFuncSetAttribute(attn_kernel, cudaFuncAttributeMaxDynamicSharedMemorySize, ATT_SMEM_BYTES);
    cudaFuncSetAttribute(out_kernel,  cudaFuncAttributeMaxDynamicSharedMemorySize, out_smem);

    zero_G_kernel<<<128, 256>>>();
    mlp_kernel<<<dim3(512, 3), 256, mlp_smem>>>(x, qw1, qb1, qw2, qb2,
                                                kw1, kb1, kw2, kb2,
                                                vw1, vb1, vw2, vb2);
    gram_kernel<<<dim3(32, 8), 256>>>();
    attn_kernel<<<dim3(16, 32), 256, ATT_SMEM_BYTES>>>();
    out_kernel<<<512, 256, out_smem>>>(x, ow, ob, lng, lnb, out);
}

// round 4
// speedup vs baseline: 1.0243x; 1.0243x over previous
#include <cuda_runtime.h>
#include <math.h>

#define BB 8
#define CC 256
#define LL 2048
#define HH 4
#define HD 64
#define NTOK (BB*LL)
#define BHN (BB*HH)

typedef unsigned long long u64;

__device__ float g_Q[BHN*LL*HD];
__device__ float g_K[BHN*LL*HD];
__device__ float g_V[BHN*LL*HD];
__device__ float g_G[BHN*HD*HD];
__device__ float g_AT[NTOK*CC];

__device__ __forceinline__ u64 dup2(float x){ u64 r; asm("mov.b64 %0,{%1,%1};":"=l"(r):"f"(x)); return r; }
__device__ __forceinline__ void unpack2(u64 v, float& lo, float& hi){ asm("mov.b64 {%0,%1},%2;":"=f"(lo),"=f"(hi):"l"(v)); }
__device__ __forceinline__ u64 fma2(u64 a,u64 b,u64 c){ u64 d; asm("fma.rn.f32x2 %0,%1,%2,%3;":"=l"(d):"l"(a),"l"(b),"l"(c)); return d; }
__device__ __forceinline__ u64 mul2(u64 a,u64 b){ u64 d; asm("mul.rn.f32x2 %0,%1,%2;":"=l"(d):"l"(a),"l"(b)); return d; }
__device__ __forceinline__ u64 add2(u64 a,u64 b){ u64 d; asm("add.rn.f32x2 %0,%1,%2;":"=l"(d):"l"(a),"l"(b)); return d; }

__device__ __forceinline__ u64 exp_poly2(u64 t){
    u64 p = dup2(2.48015873e-5f);
    p = fma2(p, t, dup2(1.98412698e-4f));
    p = fma2(p, t, dup2(1.38888889e-3f));
    p = fma2(p, t, dup2(8.33333333e-3f));
    p = fma2(p, t, dup2(4.16666667e-2f));
    p = fma2(p, t, dup2(1.66666667e-1f));
    p = fma2(p, t, dup2(0.5f));
    p = fma2(p, t, dup2(1.0f));
    p = fma2(p, t, dup2(1.0f));
    return p;
}

__device__ __forceinline__ float gelu_exact(float x) {
    return 0.5f * x * (1.0f + erff(x * 0.70710678118654752f));
}

__global__ void zero_G_kernel() {
    int n = BHN*HD*HD;
    for (int i = blockIdx.x*blockDim.x + threadIdx.x; i < n; i += gridDim.x*blockDim.x)
        g_G[i] = 0.f;
}

// ---------------- fused MLP (unchanged from passing R2) ---------------------
__global__ void __launch_bounds__(256) mlp_kernel(
    const float* __restrict__ x,
    const float* __restrict__ qw1, const float* __restrict__ qb1,
    const float* __restrict__ qw2, const float* __restrict__ qb2,
    const float* __restrict__ kw1, const float* __restrict__ kb1,
    const float* __restrict__ kw2, const float* __restrict__ kb2,
    const float* __restrict__ vw1, const float* __restrict__ vb1,
    const float* __restrict__ vw2, const float* __restrict__ vb2)
{
    extern __shared__ float sm[];
    float* xt = sm;
    float* ht = sm + 256*36;
    float* ws = sm + 2*256*36;

    const float *w1, *b1, *w2, *b2; float* out;
    if (blockIdx.y == 0)      { w1=qw1; b1=qb1; w2=qw2; b2=qb2; out=g_Q; }
    else if (blockIdx.y == 1) { w1=kw1; b1=kb1; w2=kw2; b2=kb2; out=g_K; }
    else                      { w1=vw1; b1=vb1; w2=vw2; b2=vb2; out=g_V; }

    const int b  = blockIdx.x >> 6;
    const int l0 = (blockIdx.x & 63) << 5;
    const int tid = threadIdx.x;

    const float* xb = x + (size_t)b*CC*LL + l0;
    #pragma unroll
    for (int r = 0; r < 32; r++) {
        int idx = tid + r*256;
        xt[(idx >> 5)*36 + (idx & 31)] = xb[(size_t)(idx >> 5)*LL + (idx & 31)];
    }

    const int tg = tid >> 5, fg = tid & 31;
    const int t0 = tg << 2;

    float acc[4][8];
    #pragma unroll
    for (int m = 0; m < 4; m++)
        #pragma unroll
        for (int j = 0; j < 8; j++) acc[m][j] = 0.f;

    for (int ks = 0; ks < 8; ks++) {
        __syncthreads();
        const float4* wsrc = (const float4*)(w1 + ks*32*256);
        float4* wdst = (float4*)ws;
        #pragma unroll
        for (int r = 0; r < 8; r++) wdst[tid + r*256] = wsrc[tid + r*256];
        __syncthreads();
        #pragma unroll 8
        for (int k = 0; k < 32; k++) {
            float4 a = *(const float4*)(xt + (ks*32 + k)*36 + t0);
            #pragma unroll
            for (int j = 0; j < 8; j++) {
                float bv = ws[k*256 + fg + (j<<5)];
                acc[0][j] = fmaf(a.x, bv, acc[0][j]);
                acc[1][j] = fmaf(a.y, bv, acc[1][j]);
                acc[2][j] = fmaf(a.z, bv, acc[2][j]);
                acc[3][j] = fmaf(a.w, bv, acc[3][j]);
            }
        }
    }
    __syncthreads();
    #pragma unroll
    for (int j = 0; j < 8; j++) {
        int f = fg + (j<<5);
        float bbv = b1[f];
        float4 v;
        v.x = gelu_exact(acc[0][j] + bbv);
        v.y = gelu_exact(acc[1][j] + bbv);
        v.z = gelu_exact(acc[2][j] + bbv);
        v.w = gelu_exact(acc[3][j] + bbv);
        *(float4*)(ht + f*36 + t0) = v;
        acc[0][j]=0.f; acc[1][j]=0.f; acc[2][j]=0.f; acc[3][j]=0.f;
    }

    for (int ks = 0; ks < 8; ks++) {
        __syncthreads();
        const float4* wsrc = (const float4*)(w2 + ks*32*256);
        float4* wdst = (float4*)ws;
        #pragma unroll
        for (int r = 0; r < 8; r++) wdst[tid + r*256] = wsrc[tid + r*256];
        __syncthreads();
        #pragma unroll 8
        for (int k = 0; k < 32; k++) {
            float4 a = *(const float4*)(ht + (ks*32 + k)*36 + t0);
            #pragma unroll
            for (int j = 0; j < 8; j++) {
                float bv = ws[k*256 + fg + (j<<5)];
                acc[0][j] = fmaf(a.x, bv, acc[0][j]);
                acc[1][j] = fmaf(a.y, bv, acc[1][j]);
                acc[2][j] = fmaf(a.z, bv, acc[2][j]);
                acc[3][j] = fmaf(a.w, bv, acc[3][j]);
            }
        }
    }

    #pragma unroll
    for (int j = 0; j < 8; j++) {
        int f = fg + (j<<5);
        int h = f >> 6, d = f & 63;
        float bbv = b2[f];
        float* op = out + (((size_t)(b*HH + h))*LL + l0 + t0)*HD + d;
        #pragma unroll
        for (int m = 0; m < 4; m++) op[m*HD] = acc[m][j] + bbv;
    }
}

// ---------------- Gram (unchanged) ------------------------------------------
__global__ void __launch_bounds__(256) gram_kernel() {
    __shared__ float Ks[64*68];
    const int bh = blockIdx.x, sl = blockIdx.y;
    const float* Kb = g_K + ((size_t)bh*LL + sl*256)*HD;
    const int tid = threadIdx.x;
    const int d0 = (tid >> 4) << 2, e0 = (tid & 15) << 2;
    float acc[4][4];
    #pragma unroll
    for (int i = 0; i < 4; i++)
        #pragma unroll
        for (int j = 0; j < 4; j++) acc[i][j] = 0.f;

    for (int kt = 0; kt < 4; kt++) {
        __syncthreads();
        #pragma unroll
        for (int r = 0; r < 16; r++) {
            int idx = tid + r*256;
            Ks[(idx >> 6)*68 + (idx & 63)] = Kb[kt*64*HD + idx];
        }
        __syncthreads();
        #pragma unroll 8
        for (int k = 0; k < 64; k++) {
            float4 a  = *(const float4*)(Ks + k*68 + d0);
            float4 bv = *(const float4*)(Ks + k*68 + e0);
            float av[4] = {a.x, a.y, a.z, a.w};
            float bw[4] = {bv.x, bv.y, bv.z, bv.w};
            #pragma unroll
            for (int i = 0; i < 4; i++)
                #pragma unroll
                for (int j = 0; j < 4; j++)
                    acc[i][j] = fmaf(av[i], bw[j], acc[i][j]);
        }
    }
    float* Gp = g_G + (size_t)bh*HD*HD;
    #pragma unroll
    for (int i = 0; i < 4; i++)
        #pragma unroll
        for (int j = 0; j < 4; j++)
            atomicAdd(Gp + (d0 + i)*HD + e0 + j, acc[i][j]);
}

// ---------------- attention: f32x2-packed along q ---------------------------
#define ATT_SMEM_BYTES ((64*132 + 64*132 + 128*68 + 128*132 + 3*128)*4)
__global__ void __launch_bounds__(256, 1) attn_kernel() {
    extern __shared__ float sm[];
    float* Qt   = sm;                   // [64 d][132 q]
    float* Kt   = Qt + 64*132;          // [64 d][132 k]
    float* Vs   = Kt + 64*132;          // [128 k][68 d]
    float* Pt   = Vs + 128*68;          // [128 k][132 q]
    float* invd = Pt + 128*132;
    float* psum = invd + 128;
    float* red  = psum + 128;

    const int tid = threadIdx.x;
    const int bh  = blockIdx.y;
    const int q0g = blockIdx.x << 7;

    const float* Qb = g_Q + ((size_t)bh*LL + q0g)*HD;
    #pragma unroll
    for (int r = 0; r < 32; r++) {
        int idx = tid + r*256;
        Qt[(idx & 63)*132 + (idx >> 6)] = Qb[idx];
    }
    {
        const float* Gb = g_G + (size_t)bh*HD*HD;
        #pragma unroll
        for (int r = 0; r < 16; r++) {
            int idx = tid + r*256;
            Pt[(idx >> 6)*68 + (idx & 63)] = Gb[idx];
        }
    }
    __syncthreads();

    {   // denom: ssq[q] = q^T G q ; arg = dot/(sqrt(ssq)+8e-12)
        const float* Gs = Pt;
        int q = tid & 127, half = tid >> 7;
        float part = 0.f;
        for (int d = half*32; d < half*32 + 32; d++) {
            float qd = Qt[d*132 + q];
            float t = 0.f;
            #pragma unroll 16
            for (int e = 0; e < 64; e++)
                t = fmaf(Gs[d*68 + e], Qt[e*132 + q], t);
            part = fmaf(qd, t, part);
        }
        if (half == 0) red[q] = part;
        __syncthreads();
        if (half == 1) {
            float ssq = red[q] + part;
            invd[q] = 1.0f / (sqrtf(fmaxf(ssq, 0.f)) + 8.0e-12f);
            psum[q] = 0.f;
        }
    }
    __syncthreads();

    const int ty = tid >> 4, tx = tid & 15;
    const int qr = ty << 3, kc = tx << 3, dc = tx << 2;

    u64 Oacc2[4][4];          // [q-pair][d]
    #pragma unroll
    for (int p = 0; p < 4; p++)
        #pragma unroll
        for (int c = 0; c < 4; c++) Oacc2[p][c] = 0ULL;
    u64 rs2[4] = {0ULL,0ULL,0ULL,0ULL};
    u64 invd2[4];
    #pragma unroll
    for (int p = 0; p < 4; p++) invd2[p] = ((const u64*)(invd + qr))[p];

    const float* Kb = g_K + (size_t)bh*LL*HD;
    const float* Vb = g_V + (size_t)bh*LL*HD;

    for (int kt = 0; kt < 16; kt++) {
        __syncthreads();
        const float* Ksrc = Kb + (size_t)kt*128*HD;
        const float* Vsrc = Vb + (size_t)kt*128*HD;
        #pragma unroll
        for (int r = 0; r < 32; r++) {
            int idx = tid + r*256;
            Kt[(idx & 63)*132 + (idx >> 6)] = Ksrc[idx];
            Vs[(idx >> 6)*68 + (idx & 63)]  = Vsrc[idx];
        }
        __syncthreads();

        // S = Q K^T, q packed in pairs: s2[p][j] = scores for q rows (qr+2p, qr+2p+1)
        u64 s2[4][8];
        #pragma unroll
        for (int p = 0; p < 4; p++)
            #pragma unroll
            for (int j = 0; j < 8; j++) s2[p][j] = 0ULL;
        #pragma unroll 4
        for (int d = 0; d < 64; d++) {
            ulonglong2 qa = *(const ulonglong2*)(Qt + d*132 + qr);
            ulonglong2 qb2v = *(const ulonglong2*)(Qt + d*132 + qr + 4);
            u64 qp[4] = {qa.x, qa.y, qb2v.x, qb2v.y};
            float4 k0 = *(const float4*)(Kt + d*132 + kc);
            float4 k1 = *(const float4*)(Kt + d*132 + kc + 4);
            u64 kd[8] = {dup2(k0.x), dup2(k0.y), dup2(k0.z), dup2(k0.w),
                         dup2(k1.x), dup2(k1.y), dup2(k1.z), dup2(k1.w)};
            #pragma unroll
            for (int p = 0; p < 4; p++)
                #pragma unroll
                for (int j = 0; j < 8; j++)
                    s2[p][j] = fma2(qp[p], kd[j], s2[p][j]);
        }

        // packed exp + rowsum
        #pragma unroll
        for (int p = 0; p < 4; p++) {
            #pragma unroll
            for (int j = 0; j < 8; j++) {
                u64 e = exp_poly2(mul2(s2[p][j], invd2[p]));
                s2[p][j] = e;
                rs2[p] = add2(rs2[p], e);
            }
        }
        // store P transposed [k][q] (q pairs contiguous)
        #pragma unroll
        for (int j = 0; j < 8; j++) {
            ulonglong2 lo, hi;
            lo.x = s2[0][j]; lo.y = s2[1][j];
            hi.x = s2[2][j]; hi.y = s2[3][j];
            *(ulonglong2*)(Pt + (kc + j)*132 + qr)     = lo;
            *(ulonglong2*)(Pt + (kc + j)*132 + qr + 4) = hi;
        }
        __syncthreads();

        // O += P V  (q pairs packed, V dup'd)
        #pragma unroll 4
        for (int k = 0; k < 128; k++) {
            ulonglong2 pa = *(const ulonglong2*)(Pt + k*132 + qr);
            ulonglong2 pb = *(const ulonglong2*)(Pt + k*132 + qr + 4);
            u64 pp[4] = {pa.x, pa.y, pb.x, pb.y};
            float4 vf = *(const float4*)(Vs + k*68 + dc);
            u64 vd[4] = {dup2(vf.x), dup2(vf.y), dup2(vf.z), dup2(vf.w)};
            #pragma unroll
            for (int p = 0; p < 4; p++)
                #pragma unroll
                for (int c = 0; c < 4; c++)
                    Oacc2[p][c] = fma2(pp[p], vd[c], Oacc2[p][c]);
        }
    }

    #pragma unroll
    for (int p = 0; p < 4; p++) {
        float lo, hi; unpack2(rs2[p], lo, hi);
        atomicAdd(&psum[qr + 2*p],     lo);
        atomicAdd(&psum[qr + 2*p + 1], hi);
    }
    __syncthreads();

    const int b = bh >> 2, h = bh & 3;
    #pragma unroll
    for (int p = 0; p < 4; p++) {
        float ilo = 1.0f / psum[qr + 2*p];
        float ihi = 1.0f / psum[qr + 2*p + 1];
        float olo[4], ohi[4];
        #pragma unroll
        for (int c = 0; c < 4; c++) unpack2(Oacc2[p][c], olo[c], ohi[c]);
        size_t row0 = (size_t)(b*LL + q0g + qr + 2*p)*CC + h*HD + dc;
        size_t row1 = row0 + CC;
        *(float4*)(g_AT + row0) = make_float4(olo[0]*ilo, olo[1]*ilo, olo[2]*ilo, olo[3]*ilo);
        *(float4*)(g_AT + row1) = make_float4(ohi[0]*ihi, ohi[1]*ihi, ohi[2]*ihi, ohi[3]*ihi);
    }
}

// ---------------- O-proj + LN + ELU + residual (unchanged) ------------------
__global__ void __launch_bounds__(256) out_kernel(
    const float* __restrict__ x_in, const float* __restrict__ ow,
    const float* __restrict__ ob, const float* __restrict__ lng,
    const float* __restrict__ lnb, float* __restrict__ out)
{
    extern __shared__ float sm[];
    float* at = sm;
    float* ws = sm + 256*36;

    const int tok0 = blockIdx.x << 5;
    const int b = tok0 >> 11, l0 = tok0 & (LL-1);
    const int tid = threadIdx.x;

    #pragma unroll
    for (int r = 0; r < 32; r++) {
        int idx = tid + r*256;
        int t = idx >> 8, k = idx & 255;
        at[k*36 + t] = g_AT[(size_t)(tok0 + t)*CC + k];
    }

    const int tg = tid >> 5, fg = tid & 31;
    const int t0 = tg << 2;

    float acc[4][8];
    #pragma unroll
    for (int m = 0; m < 4; m++)
        #pragma unroll
        for (int j = 0; j < 8; j++) acc[m][j] = 0.f;

    for (int ks = 0; ks < 8; ks++) {
        __syncthreads();
        const float4* wsrc = (const float4*)(ow + ks*32*256);
        float4* wdst = (float4*)ws;
        #pragma unroll
        for (int r = 0; r < 8; r++) wdst[tid + r*256] = wsrc[tid + r*256];
        __syncthreads();
        #pragma unroll 8
        for (int k = 0; k < 32; k++) {
            float4 a = *(const float4*)(at + (ks*32 + k)*36 + t0);
            #pragma unroll
            for (int j = 0; j < 8; j++) {
                float bv = ws[k*256 + fg + (j<<5)];
                acc[0][j] = fmaf(a.x, bv, acc[0][j]);
                acc[1][j] = fmaf(a.y, bv, acc[1][j]);
                acc[2][j] = fmaf(a.z, bv, acc[2][j]);
                acc[3][j] = fmaf(a.w, bv, acc[3][j]);
            }
        }
    }

    float gv[8], bvv[8];
    #pragma unroll
    for (int j = 0; j < 8; j++) {
        int f = fg + (j<<5);
        acc[0][j] += ob[f]; acc[1][j] += ob[f]; acc[2][j] += ob[f]; acc[3][j] += ob[f];
        gv[j] = lng[f]; bvv[j] = lnb[f];
    }
    __syncthreads();
    #pragma unroll
    for (int m = 0; m < 4; m++) {
        float s = 0.f, s2v = 0.f;
        #pragma unroll
        for (int j = 0; j < 8; j++) { s += acc[m][j]; s2v = fmaf(acc[m][j], acc[m][j], s2v); }
        #pragma unroll
        for (int o = 16; o > 0; o >>= 1) {
            s   += __shfl_xor_sync(0xffffffffu, s,   o);
            s2v += __shfl_xor_sync(0xffffffffu, s2v, o);
        }
        float mu = s * (1.0f/256.0f);
        float var = fmaf(-mu, mu, s2v * (1.0f/256.0f));
        float rstd = rsqrtf(var + 1e-5f);
        #pragma unroll
        for (int j = 0; j < 8; j++) {
            int f = fg + (j<<5);
            at[f*36 + t0 + m] = fmaf((acc[m][j] - mu) * rstd, gv[j], bvv[j]);
        }
    }
    __syncthreads();

    const float* xb = x_in + (size_t)b*CC*LL + l0;
    float* outb = out + (size_t)b*CC*LL + l0;
    #pragma unroll
    for (int r = 0; r < 32; r++) {
        int idx = tid + r*256;
        int t = idx & 31, f = idx >> 5;
        float y = at[f*36 + t];
        float e = (y > 0.f) ? y : expm1f(y);
        outb[(size_t)f*LL + t] = e + xb[(size_t)f*LL + t];
    }
}

extern "C" void kernel_launch(void* const* d_in, const int* in_sizes, int n_in,
                              void* d_out, int out_size) {
    const float* x    = (const float*)d_in[0];
    const float* qw1  = (const float*)d_in[1];
    const float* qb1  = (const float*)d_in[2];
    const float* qw2  = (const float*)d_in[3];
    const float* qb2  = (const float*)d_in[4];
    const float* kw1  = (const float*)d_in[5];
    const float* kb1  = (const float*)d_in[6];
    const float* kw2  = (const float*)d_in[7];
    const float* kb2  = (const float*)d_in[8];
    const float* vw1  = (const float*)d_in[9];
    const float* vb1  = (const float*)d_in[10];
    const float* vw2  = (const float*)d_in[11];
    const float* vb2  = (const float*)d_in[12];
    const float* ow   = (const float*)d_in[13];
    const float* ob   = (const float*)d_in[14];
    const float* lng  = (const float*)d_in[15];
    const float* lnb  = (const float*)d_in[16];
    float* out = (float*)d_out;

    const int mlp_smem = (2*256*36 + 32*256)*4;
    const int out_smem = (256*36 + 32*256)*4;
    cudaFuncSetAttribute(mlp_kernel,  cudaFuncAttributeMaxDynamicSharedMemorySize, mlp_smem);
    cudaFuncSetAttribute(attn_kernel, cudaFuncAttributeMaxDynamicSharedMemorySize, ATT_SMEM_BYTES);
    cudaFuncSetAttribute(out_kernel,  cudaFuncAttributeMaxDynamicSharedMemorySize, out_smem);

    zero_G_kernel<<<128, 256>>>();
    mlp_kernel<<<dim3(512, 3), 256, mlp_smem>>>(x, qw1, qb1, qw2, qb2,
                                                kw1, kb1, kw2, kb2,
                                                vw1, vb1, vw2, vb2);
    gram_kernel<<<dim3(32, 8), 256>>>();
    attn_kernel<<<dim3(16, 32), 256, ATT_SMEM_BYTES>>>();
    out_kernel<<<512, 256, out_smem>>>(x, ow, ob, lng, lnb, out);
}